// round 1
// baseline (speedup 1.0000x reference)
#include <cuda_runtime.h>

#define NHEAD 8
#define HD 128
#define BSZ 1024
#define CDIM (NHEAD*HD)
#define BT 32          // batches per CTA
#define NBG 8          // batches per group (== warps per CTA)
#define THREADS 256
#define WPITCH 129     // smem pitch for transposed weights (conflict-free)

__device__ __forceinline__ float ex2f(float x) {
    float y;
    asm("ex2.approx.ftz.f32 %0, %1;" : "=f"(y) : "f"(x));
    return y;
}
__device__ __forceinline__ float rcpf(float x) {
    float y;
    asm("rcp.approx.ftz.f32 %0, %1;" : "=f"(y) : "f"(x));
    return y;
}

__global__ __launch_bounds__(THREADS) void satt_kernel(
    const float* __restrict__ x,
    const float* __restrict__ Wq,
    const float* __restrict__ Wkv,
    float* __restrict__ out)
{
    extern __shared__ float s[];
    float*  Wq_s = s;                        // [128][WPITCH] transposed: Wq_s[d][e]
    float*  Wk_s = s + HD*WPITCH;
    float*  Wv_s = s + 2*HD*WPITCH;
    float*  x_s  = s + 3*HD*WPITCH;          // [NBG][HD]
    float*  q_s  = x_s + NBG*HD;             // [NBG][HD]
    float2* kv_s = (float2*)(q_s + NBG*HD);  // [NBG][HD]  (k*scale*log2e, v)

    const int h   = blockIdx.y;
    const int tid = threadIdx.x;

    // ---- load weights (transposed into smem) ----
    const float* Wqh = Wq  + (size_t)h*HD*HD;
    const float* Wkh = Wkv + (size_t)h*2*HD*HD;
    const float* Wvh = Wkh + HD*HD;
    #pragma unroll 4
    for (int i = tid; i < HD*HD; i += THREADS) {
        int e = i >> 7, d = i & 127;
        Wq_s[d*WPITCH + e] = Wqh[i];
        Wk_s[d*WPITCH + e] = Wkh[i];
        Wv_s[d*WPITCH + e] = Wvh[i];
    }
    __syncthreads();

    // scale = HD^-0.5 * log2(e), folded into k so exp() becomes one EX2
    const float kscale = 0.08838834764831845f * 1.4426950408889634f;

    const int sub  = tid >> 7;    // 0/1 : which 4-batch half this thread projects
    const int j    = tid & 127;   // output column
    const int warp = tid >> 5;    // attention: warp -> local batch
    const int lane = tid & 31;

    for (int g = 0; g < BT/NBG; ++g) {
        const int b0 = blockIdx.x * BT + g * NBG;

        // ---- load x tile ----
        for (int i = tid; i < NBG*HD; i += THREADS) {
            int b = i >> 7, d = i & 127;
            x_s[i] = x[(size_t)(b0 + b)*CDIM + h*HD + d];
        }
        __syncthreads();

        // ---- projections: q/k/v[j] for 4 batches each (register-tiled) ----
        float qa[4] = {0,0,0,0}, ka[4] = {0,0,0,0}, va[4] = {0,0,0,0};
        const float* xb = x_s + sub*4*HD;
        #pragma unroll 4
        for (int d = 0; d < HD; ++d) {
            float wq = Wq_s[d*WPITCH + j];
            float wk = Wk_s[d*WPITCH + j];
            float wv = Wv_s[d*WPITCH + j];
            #pragma unroll
            for (int b = 0; b < 4; ++b) {
                float xv = xb[b*HD + d];
                qa[b] = fmaf(wq, xv, qa[b]);
                ka[b] = fmaf(wk, xv, ka[b]);
                va[b] = fmaf(wv, xv, va[b]);
            }
        }
        #pragma unroll
        for (int b = 0; b < 4; ++b) {
            int bl = sub*4 + b;
            q_s[bl*HD + j]  = qa[b];
            kv_s[bl*HD + j] = make_float2(ka[b]*kscale, va[b]);
        }
        __syncthreads();

        // ---- attention: warp w -> batch w; lane covers d = lane + 32*i ----
        {
            const int bl = warp;
            const float2* kvb = kv_s + bl*HD;
            float qd[4], num[4] = {0,0,0,0}, den[4] = {0,0,0,0};
            #pragma unroll
            for (int i = 0; i < 4; ++i) qd[i] = q_s[bl*HD + lane + 32*i];
            #pragma unroll 4
            for (int e = 0; e < HD; ++e) {
                float2 kv = kvb[e];
                #pragma unroll
                for (int i = 0; i < 4; ++i) {
                    float p = ex2f(qd[i] * kv.x);   // exp(q_d * k_e * scale)
                    num[i] = fmaf(p, kv.y, num[i]);
                    den[i] += p;
                }
            }
            float* outb = out + (size_t)(b0 + bl)*CDIM + h*HD;
            #pragma unroll
            for (int i = 0; i < 4; ++i)
                outb[lane + 32*i] = num[i] * rcpf(den[i]);
        }
        __syncthreads();
    }
}

extern "C" void kernel_launch(void* const* d_in, const int* in_sizes, int n_in,
                              void* d_out, int out_size) {
    const float* x   = (const float*)d_in[0];
    const float* Wq  = (const float*)d_in[1];
    const float* Wkv = (const float*)d_in[2];
    float* out = (float*)d_out;

    const size_t smem = (3*HD*WPITCH + NBG*HD /*x*/ + NBG*HD /*q*/ + 2*NBG*HD /*kv*/) * sizeof(float);
    cudaFuncSetAttribute(satt_kernel, cudaFuncAttributeMaxDynamicSharedMemorySize, (int)smem);

    dim3 grid(BSZ/BT, NHEAD);
    satt_kernel<<<grid, THREADS, smem>>>(x, Wq, Wkv, out);
}

// round 2
// speedup vs baseline: 1.5354x; 1.5354x over previous
#include <cuda_runtime.h>

#define NHEAD 8
#define HD 128
#define BSZ 1024
#define CDIM (NHEAD*HD)
#define NB 32              // batches per CTA
#define THREADS 384        // 3 groups of 128: q / k / v projection columns
#define SCALE 0.08838834764831845f   // HD^-0.5

__device__ __forceinline__ float rcpf(float x) {
    float y;
    asm("rcp.approx.ftz.f32 %0, %1;" : "=f"(y) : "f"(x));
    return y;
}

__global__ __launch_bounds__(THREADS) void satt_kernel(
    const float* __restrict__ x,
    const float* __restrict__ Wq,
    const float* __restrict__ Wkv,
    float* __restrict__ out)
{
    extern __shared__ float s[];
    float* x_s = s;                 // [NB][HD]
    float* q_s = s + NB*HD;         // [NB][HD]
    float* k_s = s + 2*NB*HD;       // [NB][HD], pre-scaled by SCALE
    float* v_s = s + 3*NB*HD;       // [NB][HD]

    const int h   = blockIdx.y;
    const int b0  = blockIdx.x * NB;
    const int tid = threadIdx.x;

    // ---- stage x tile ----
    for (int i = tid; i < NB*HD; i += THREADS) {
        int b = i >> 7, d = i & 127;
        x_s[i] = x[(size_t)(b0 + b)*CDIM + h*HD + d];
    }
    __syncthreads();

    // ---- projections: thread (m, e) computes {q|k|v}[e] for all NB batches ----
    const int m = tid >> 7;          // 0=q, 1=k, 2=v
    const int e = tid & 127;
    const float* Wbase = (m == 0) ? (Wq + (size_t)h*HD*HD)
                                  : (Wkv + (size_t)h*2*HD*HD + (m == 2 ? HD*HD : 0));
    const float4* Wrow = (const float4*)(Wbase + (size_t)e*HD);

    float acc[NB];
    #pragma unroll
    for (int b = 0; b < NB; ++b) acc[b] = 0.f;

    #pragma unroll 2
    for (int c = 0; c < HD/4; ++c) {
        float4 w = __ldg(&Wrow[c]);
        const float4* xs4 = (const float4*)x_s + c;
        #pragma unroll
        for (int b = 0; b < NB; ++b) {
            float4 xv = xs4[b*(HD/4)];
            acc[b] = fmaf(w.x, xv.x, acc[b]);
            acc[b] = fmaf(w.y, xv.y, acc[b]);
            acc[b] = fmaf(w.z, xv.z, acc[b]);
            acc[b] = fmaf(w.w, xv.w, acc[b]);
        }
    }
    {
        float sc = (m == 1) ? SCALE : 1.0f;
        float* dst = (m == 0) ? q_s : (m == 1) ? k_s : v_s;
        #pragma unroll
        for (int b = 0; b < NB; ++b) dst[b*HD + e] = acc[b] * sc;
    }
    __syncthreads();

    // ---- attention via separable moment expansion ----
    // out_d = [sum_n (q_d^n/n!) S_n] / [sum_n (q_d^n/n!) K_n],
    //   K_n = sum_e kappa^n,  S_n = sum_e kappa^n v_e,  kappa = k*SCALE
    const int warp = tid >> 5, lane = tid & 31;
    for (int b = warp; b < NB; b += THREADS/32) {
        float K1=0,K2=0,K3=0,K4=0,K5=0,K6=0,K7=0,K8=0;
        float S0=0,S1=0,S2=0,S3=0,S4=0,S5=0,S6=0,S7=0,S8=0;
        #pragma unroll
        for (int i = 0; i < 4; ++i) {
            float kk = k_s[b*HD + lane + 32*i];
            float vv = v_s[b*HD + lane + 32*i];
            float t = kk;
            S0 += vv;
            K1 += t; S1 = fmaf(t, vv, S1); t *= kk;
            K2 += t; S2 = fmaf(t, vv, S2); t *= kk;
            K3 += t; S3 = fmaf(t, vv, S3); t *= kk;
            K4 += t; S4 = fmaf(t, vv, S4); t *= kk;
            K5 += t; S5 = fmaf(t, vv, S5); t *= kk;
            K6 += t; S6 = fmaf(t, vv, S6); t *= kk;
            K7 += t; S7 = fmaf(t, vv, S7); t *= kk;
            K8 += t; S8 = fmaf(t, vv, S8);
        }
        #pragma unroll
        for (int off = 16; off > 0; off >>= 1) {
            K1 += __shfl_xor_sync(~0u, K1, off);
            K2 += __shfl_xor_sync(~0u, K2, off);
            K3 += __shfl_xor_sync(~0u, K3, off);
            K4 += __shfl_xor_sync(~0u, K4, off);
            K5 += __shfl_xor_sync(~0u, K5, off);
            K6 += __shfl_xor_sync(~0u, K6, off);
            K7 += __shfl_xor_sync(~0u, K7, off);
            K8 += __shfl_xor_sync(~0u, K8, off);
            S0 += __shfl_xor_sync(~0u, S0, off);
            S1 += __shfl_xor_sync(~0u, S1, off);
            S2 += __shfl_xor_sync(~0u, S2, off);
            S3 += __shfl_xor_sync(~0u, S3, off);
            S4 += __shfl_xor_sync(~0u, S4, off);
            S5 += __shfl_xor_sync(~0u, S5, off);
            S6 += __shfl_xor_sync(~0u, S6, off);
            S7 += __shfl_xor_sync(~0u, S7, off);
            S8 += __shfl_xor_sync(~0u, S8, off);
        }
        // fold 1/n!
        const float a0 = 128.0f;
        const float a1 = K1,                 g0 = S0;
        const float a2 = K2*0.5f,            g1 = S1;
        const float a3 = K3*(1.f/6.f),       g2 = S2*0.5f;
        const float a4 = K4*(1.f/24.f),      g3 = S3*(1.f/6.f);
        const float a5 = K5*(1.f/120.f),     g4 = S4*(1.f/24.f);
        const float a6 = K6*(1.f/720.f),     g5 = S5*(1.f/120.f);
        const float a7 = K7*(1.f/5040.f),    g6 = S6*(1.f/720.f);
        const float a8 = K8*(1.f/40320.f),   g7 = S7*(1.f/5040.f);
        const float g8 = S8*(1.f/40320.f);

        float* outb = out + (size_t)(b0 + b)*CDIM + h*HD;
        #pragma unroll
        for (int i = 0; i < 4; ++i) {
            int d = lane + 32*i;
            float q = q_s[b*HD + d];
            float den = fmaf(a8, q, a7);
            den = fmaf(den, q, a6); den = fmaf(den, q, a5);
            den = fmaf(den, q, a4); den = fmaf(den, q, a3);
            den = fmaf(den, q, a2); den = fmaf(den, q, a1);
            den = fmaf(den, q, a0);
            float num = fmaf(g8, q, g7);
            num = fmaf(num, q, g6); num = fmaf(num, q, g5);
            num = fmaf(num, q, g4); num = fmaf(num, q, g3);
            num = fmaf(num, q, g2); num = fmaf(num, q, g1);
            num = fmaf(num, q, g0);
            outb[d] = num * rcpf(den);
        }
    }
}

extern "C" void kernel_launch(void* const* d_in, const int* in_sizes, int n_in,
                              void* d_out, int out_size) {
    const float* x   = (const float*)d_in[0];
    const float* Wq  = (const float*)d_in[1];
    const float* Wkv = (const float*)d_in[2];
    float* out = (float*)d_out;

    const size_t smem = 4 * NB * HD * sizeof(float);   // 64 KB
    cudaFuncSetAttribute(satt_kernel, cudaFuncAttributeMaxDynamicSharedMemorySize, (int)smem);

    dim3 grid(BSZ/NB, NHEAD);
    satt_kernel<<<grid, THREADS, smem>>>(x, Wq, Wkv, out);
}

// round 5
// speedup vs baseline: 3.4043x; 2.2171x over previous
#include <cuda_runtime.h>
#include <cuda_bf16.h>
#include <cstdint>

#define NHEAD 8
#define HD 128
#define BSZ 1024
#define CDIM 1024
#define NB 64
#define THREADS 512
#define SCALE 0.08838834764831845f   // HD^-0.5

#define XPITCH 136   // bf16 elems per row
#define WPITCH 136
#define QPITCH 129   // f32 elems per row

// ---- smem byte offsets ----
#define SM_XHI  0
#define SM_XLO  17408
#define SM_WHI  34816
#define SM_WLO  69632
#define SM_QKV  104448              // float[3][64][QPITCH]
#define SM_TOTAL 203520
// overlays (live only after mma stage is complete)
#define SM_RED  SM_WHI              // float[8][64][13]
#define SM_COEF (SM_WHI + 26624)    // float[64][13]
#define SM_OUTS SM_XHI              // float[64][QPITCH]

__device__ __forceinline__ float rcpf(float x) {
    float y; asm("rcp.approx.ftz.f32 %0, %1;" : "=f"(y) : "f"(x)); return y;
}

__device__ __forceinline__ void mma_bf16(float c[4],
    uint32_t a0, uint32_t a1, uint32_t a2, uint32_t a3,
    uint32_t b0, uint32_t b1)
{
    asm volatile(
        "mma.sync.aligned.m16n8k16.row.col.f32.bf16.bf16.f32 "
        "{%0,%1,%2,%3}, {%4,%5,%6,%7}, {%8,%9}, {%0,%1,%2,%3};"
        : "+f"(c[0]), "+f"(c[1]), "+f"(c[2]), "+f"(c[3])
        : "r"(a0), "r"(a1), "r"(a2), "r"(a3), "r"(b0), "r"(b1));
}

__device__ __forceinline__ uint32_t bits2(__nv_bfloat162 v) {
    return *reinterpret_cast<uint32_t*>(&v);
}

__global__ __launch_bounds__(THREADS) void satt_kernel(
    const float* __restrict__ x,
    const float* __restrict__ Wq,
    const float* __restrict__ Wkv,
    float* __restrict__ out)
{
    extern __shared__ char smem[];
    const int tid  = threadIdx.x;
    const int wid  = tid >> 5, lane = tid & 31;
    const int g    = lane >> 2, tg = lane & 3;
    const int h    = blockIdx.y;
    const int b0   = blockIdx.x * NB;

    // ================= stage x (hi/lo bf16) =================
    #pragma unroll
    for (int j = 0; j < 4; ++j) {
        int i4 = tid + j * 512;               // float4 index over 64x128
        int b  = i4 >> 5, dq = (i4 & 31) * 4;
        float4 f = *(const float4*)(x + (size_t)(b0 + b) * CDIM + h * HD + dq);
        __nv_bfloat162 h01 = __floats2bfloat162_rn(f.x, f.y);
        __nv_bfloat162 h23 = __floats2bfloat162_rn(f.z, f.w);
        __nv_bfloat162 l01 = __floats2bfloat162_rn(f.x - __bfloat162float(h01.x),
                                                   f.y - __bfloat162float(h01.y));
        __nv_bfloat162 l23 = __floats2bfloat162_rn(f.z - __bfloat162float(h23.x),
                                                   f.w - __bfloat162float(h23.y));
        uint32_t* ph = (uint32_t*)(smem + SM_XHI + (size_t)(b * XPITCH + dq) * 2);
        uint32_t* pl = (uint32_t*)(smem + SM_XLO + (size_t)(b * XPITCH + dq) * 2);
        ph[0] = bits2(h01); ph[1] = bits2(h23);
        pl[0] = bits2(l01); pl[1] = bits2(l23);
    }

    // ================= 3 GEMMs via mma.sync =================
    const float* Wsrc[3] = { Wq  + (size_t)h * HD * HD,
                             Wkv + (size_t)h * 2 * HD * HD,
                             Wkv + (size_t)h * 2 * HD * HD + HD * HD };
    const int mg = wid >> 3;              // 0/1: which 32-batch half
    const int n0 = (wid & 7) * 16;        // 16 output cols per warp

    for (int m = 0; m < 3; ++m) {
        // ---- stage W_m hi/lo (fold SCALE into k-matrix) ----
        const float wscl = (m == 1) ? SCALE : 1.0f;
        const float* Wm = Wsrc[m];
        #pragma unroll
        for (int j = 0; j < 8; ++j) {
            int i4 = tid + j * 512;           // float4 index over 128x128
            int n  = i4 >> 5, dq = (i4 & 31) * 4;
            float4 f = *(const float4*)(Wm + (size_t)n * HD + dq);
            f.x *= wscl; f.y *= wscl; f.z *= wscl; f.w *= wscl;
            __nv_bfloat162 h01 = __floats2bfloat162_rn(f.x, f.y);
            __nv_bfloat162 h23 = __floats2bfloat162_rn(f.z, f.w);
            __nv_bfloat162 l01 = __floats2bfloat162_rn(f.x - __bfloat162float(h01.x),
                                                       f.y - __bfloat162float(h01.y));
            __nv_bfloat162 l23 = __floats2bfloat162_rn(f.z - __bfloat162float(h23.x),
                                                       f.w - __bfloat162float(h23.y));
            uint32_t* ph = (uint32_t*)(smem + SM_WHI + (size_t)(n * WPITCH + dq) * 2);
            uint32_t* pl = (uint32_t*)(smem + SM_WLO + (size_t)(n * WPITCH + dq) * 2);
            ph[0] = bits2(h01); ph[1] = bits2(h23);
            pl[0] = bits2(l01); pl[1] = bits2(l23);
        }
        __syncthreads();

        // ---- warp mma: 2 Mtiles x 2 Ntiles, hi/lo 3-pass ----
        float acc[2][2][4];
        #pragma unroll
        for (int a = 0; a < 2; ++a)
            #pragma unroll
            for (int b = 0; b < 2; ++b)
                #pragma unroll
                for (int c = 0; c < 4; ++c) acc[a][b][c] = 0.f;

        #pragma unroll
        for (int kt = 0; kt < 8; ++kt) {
            const int k0 = kt * 16;
            uint32_t A[2][2][4];   // [Mt][hi/lo][frag]
            #pragma unroll
            for (int Mt = 0; Mt < 2; ++Mt) {
                int r = mg * 32 + Mt * 16 + g;
                const char* xh = smem + SM_XHI;
                const char* xl = smem + SM_XLO;
                A[Mt][0][0] = *(const uint32_t*)(xh + (size_t)(r * XPITCH + k0 + 2*tg) * 2);
                A[Mt][0][1] = *(const uint32_t*)(xh + (size_t)((r+8) * XPITCH + k0 + 2*tg) * 2);
                A[Mt][0][2] = *(const uint32_t*)(xh + (size_t)(r * XPITCH + k0 + 8 + 2*tg) * 2);
                A[Mt][0][3] = *(const uint32_t*)(xh + (size_t)((r+8) * XPITCH + k0 + 8 + 2*tg) * 2);
                A[Mt][1][0] = *(const uint32_t*)(xl + (size_t)(r * XPITCH + k0 + 2*tg) * 2);
                A[Mt][1][1] = *(const uint32_t*)(xl + (size_t)((r+8) * XPITCH + k0 + 2*tg) * 2);
                A[Mt][1][2] = *(const uint32_t*)(xl + (size_t)(r * XPITCH + k0 + 8 + 2*tg) * 2);
                A[Mt][1][3] = *(const uint32_t*)(xl + (size_t)((r+8) * XPITCH + k0 + 8 + 2*tg) * 2);
            }
            uint32_t Bf[2][2][2];  // [Nt][hi/lo][frag]
            #pragma unroll
            for (int Nt = 0; Nt < 2; ++Nt) {
                int n = n0 + Nt * 8 + g;
                const char* wh = smem + SM_WHI;
                const char* wl = smem + SM_WLO;
                Bf[Nt][0][0] = *(const uint32_t*)(wh + (size_t)(n * WPITCH + k0 + 2*tg) * 2);
                Bf[Nt][0][1] = *(const uint32_t*)(wh + (size_t)(n * WPITCH + k0 + 8 + 2*tg) * 2);
                Bf[Nt][1][0] = *(const uint32_t*)(wl + (size_t)(n * WPITCH + k0 + 2*tg) * 2);
                Bf[Nt][1][1] = *(const uint32_t*)(wl + (size_t)(n * WPITCH + k0 + 8 + 2*tg) * 2);
            }
            #pragma unroll
            for (int Mt = 0; Mt < 2; ++Mt)
                #pragma unroll
                for (int Nt = 0; Nt < 2; ++Nt) {
                    mma_bf16(acc[Mt][Nt], A[Mt][0][0], A[Mt][0][1], A[Mt][0][2], A[Mt][0][3],
                             Bf[Nt][0][0], Bf[Nt][0][1]);   // hi*hi
                    mma_bf16(acc[Mt][Nt], A[Mt][0][0], A[Mt][0][1], A[Mt][0][2], A[Mt][0][3],
                             Bf[Nt][1][0], Bf[Nt][1][1]);   // hi*lo
                    mma_bf16(acc[Mt][Nt], A[Mt][1][0], A[Mt][1][1], A[Mt][1][2], A[Mt][1][3],
                             Bf[Nt][0][0], Bf[Nt][0][1]);   // lo*hi
                }
        }

        // ---- write fragments to qkv smem ----
        float* dst = (float*)(smem + SM_QKV) + (size_t)m * NB * QPITCH;
        #pragma unroll
        for (int Mt = 0; Mt < 2; ++Mt)
            #pragma unroll
            for (int Nt = 0; Nt < 2; ++Nt) {
                int r = mg * 32 + Mt * 16 + g;
                int c = n0 + Nt * 8 + 2 * tg;
                dst[r * QPITCH + c]         = acc[Mt][Nt][0];
                dst[r * QPITCH + c + 1]     = acc[Mt][Nt][1];
                dst[(r + 8) * QPITCH + c]     = acc[Mt][Nt][2];
                dst[(r + 8) * QPITCH + c + 1] = acc[Mt][Nt][3];
            }
        __syncthreads();   // before W restage / epilogue
    }

    // ================= epilogue: separable moment softmax =================
    const float* q_s = (const float*)(smem + SM_QKV);
    const float* k_s = q_s + NB * QPITCH;
    const float* v_s = q_s + 2 * NB * QPITCH;
    float* red  = (float*)(smem + SM_RED);
    float* coef = (float*)(smem + SM_COEF);
    float* outs = (float*)(smem + SM_OUTS);

    // Phase A: per-thread partial moments (batch = tid&63, e-part = tid>>6)
    {
        const int b = tid & 63, part = tid >> 6;
        float K1=0,K2=0,K3=0,K4=0,K5=0,K6=0;
        float S0=0,S1=0,S2=0,S3=0,S4=0,S5=0,S6=0;
        #pragma unroll
        for (int i = 0; i < 16; ++i) {
            int e = part * 16 + i;
            float kv = k_s[b * QPITCH + e];   // already scaled by SCALE
            float vv = v_s[b * QPITCH + e];
            S0 += vv;
            float t = kv; K1 += t; S1 = fmaf(t, vv, S1);
            t *= kv;      K2 += t; S2 = fmaf(t, vv, S2);
            t *= kv;      K3 += t; S3 = fmaf(t, vv, S3);
            t *= kv;      K4 += t; S4 = fmaf(t, vv, S4);
            t *= kv;      K5 += t; S5 = fmaf(t, vv, S5);
            t *= kv;      K6 += t; S6 = fmaf(t, vv, S6);
        }
        float* r = red + ((size_t)part * 64 + b) * 13;
        r[0]=K1; r[1]=K2; r[2]=K3; r[3]=K4; r[4]=K5; r[5]=K6;
        r[6]=S0; r[7]=S1; r[8]=S2; r[9]=S3; r[10]=S4; r[11]=S5; r[12]=S6;
    }
    __syncthreads();

    // Phase B: combine parts + fold 1/n!
    if (tid < 64) {
        float c[13];
        #pragma unroll
        for (int j = 0; j < 13; ++j) c[j] = 0.f;
        #pragma unroll
        for (int p = 0; p < 8; ++p) {
            const float* r = red + ((size_t)p * 64 + tid) * 13;
            #pragma unroll
            for (int j = 0; j < 13; ++j) c[j] += r[j];
        }
        float* cc = coef + tid * 13;
        cc[0] = c[0];              cc[1] = c[1] * 0.5f;
        cc[2] = c[2] * (1.f/6.f);  cc[3] = c[3] * (1.f/24.f);
        cc[4] = c[4] * (1.f/120.f);cc[5] = c[5] * (1.f/720.f);
        cc[6] = c[6];              cc[7] = c[7];
        cc[8] = c[8] * 0.5f;       cc[9] = c[9] * (1.f/6.f);
        cc[10]= c[10]* (1.f/24.f); cc[11]= c[11]* (1.f/120.f);
        cc[12]= c[12]* (1.f/720.f);
    }
    __syncthreads();

    // Phase C: Horner per (batch, 16-d chunk)  ->  outs (overlays x region)
    {
        const int b = tid & 63, part = tid >> 6;
        const float* cc = coef + b * 13;
        const float a1=cc[0],a2=cc[1],a3=cc[2],a4=cc[3],a5=cc[4],a6=cc[5];
        const float g0=cc[6],g1=cc[7],g2=cc[8],g3=cc[9],g4=cc[10],g5=cc[11],g6=cc[12];
        #pragma unroll
        for (int i = 0; i < 16; ++i) {
            int d = part * 16 + i;
            float q = q_s[b * QPITCH + d];
            float den = fmaf(a6, q, a5);
            den = fmaf(den, q, a4); den = fmaf(den, q, a3);
            den = fmaf(den, q, a2); den = fmaf(den, q, a1);
            den = fmaf(den, q, 128.0f);
            float num = fmaf(g6, q, g5);
            num = fmaf(num, q, g4); num = fmaf(num, q, g3);
            num = fmaf(num, q, g2); num = fmaf(num, q, g1);
            num = fmaf(num, q, g0);
            outs[b * QPITCH + d] = num * rcpf(den);
        }
    }
    __syncthreads();

    // coalesced copy out
    {
        const int b = tid >> 3, ds = (tid & 7) * 16;
        float* dst = out + (size_t)(b0 + b) * CDIM + h * HD + ds;
        #pragma unroll
        for (int j = 0; j < 4; ++j) {
            float4 v;
            v.x = outs[b * QPITCH + ds + j*4 + 0];
            v.y = outs[b * QPITCH + ds + j*4 + 1];
            v.z = outs[b * QPITCH + ds + j*4 + 2];
            v.w = outs[b * QPITCH + ds + j*4 + 3];
            *(float4*)(dst + j*4) = v;
        }
    }
}

extern "C" void kernel_launch(void* const* d_in, const int* in_sizes, int n_in,
                              void* d_out, int out_size) {
    const float* x   = (const float*)d_in[0];
    const float* Wq  = (const float*)d_in[1];
    const float* Wkv = (const float*)d_in[2];
    float* out = (float*)d_out;

    cudaFuncSetAttribute(satt_kernel, cudaFuncAttributeMaxDynamicSharedMemorySize, SM_TOTAL);
    dim3 grid(BSZ / NB, NHEAD);
    satt_kernel<<<grid, THREADS, SM_TOTAL>>>(x, Wq, Wkv, out);
}

// round 6
// speedup vs baseline: 3.5997x; 1.0574x over previous
#include <cuda_runtime.h>
#include <cuda_bf16.h>
#include <cstdint>

#define NHEAD 8
#define HD 128
#define BSZ 1024
#define CDIM 1024
#define NB 64
#define THREADS 512
#define SCALE 0.08838834764831845f   // HD^-0.5

#define XPITCH 136    // bf16 elems per x row (conflict-free frag loads)
#define WROWB 144     // bytes per W row in stage buffer (72 bf16 pitch, 64 used)
#define QPITCH 129    // f32 elems per row

// ---- smem byte offsets ----
#define SM_XHI   0                    // 64*136*2 = 17408
#define SM_XLO   17408
#define SM_WB    34816                // 2 stage buffers * 36864
#define WBUF_SZ  36864                // hi(128*144) + lo(128*144)
#define SM_QKV   108544               // float[3][64][QPITCH] = 99072
#define SM_TOTAL 207616
// epilogue overlays (dead regions)
#define SM_RED   34816                // float[8][64][13] = 26624
#define SM_COEF  61440                // float[64][13]
#define SM_OUTS  0                    // float[64][QPITCH] = 33024

// ---- precomputed bf16 hi/lo weights: [head][matrix][n][k] ----
__device__ __nv_bfloat16 g_whi[NHEAD * 3 * HD * HD];
__device__ __nv_bfloat16 g_wlo[NHEAD * 3 * HD * HD];

__device__ __forceinline__ float rcpf(float x) {
    float y; asm("rcp.approx.ftz.f32 %0, %1;" : "=f"(y) : "f"(x)); return y;
}
__device__ __forceinline__ uint32_t smem_u32(const void* p) {
    uint32_t a;
    asm("{ .reg .u64 t; cvta.to.shared.u64 t, %1; cvt.u32.u64 %0, t; }" : "=r"(a) : "l"(p));
    return a;
}
__device__ __forceinline__ void cp_async16(uint32_t dst, const void* src) {
    asm volatile("cp.async.ca.shared.global [%0], [%1], 16;" :: "r"(dst), "l"(src) : "memory");
}
#define CP_COMMIT() asm volatile("cp.async.commit_group;" ::: "memory")
#define CP_WAIT0()  asm volatile("cp.async.wait_group 0;" ::: "memory")

__device__ __forceinline__ void mma_bf16(float c[4],
    uint32_t a0, uint32_t a1, uint32_t a2, uint32_t a3,
    uint32_t b0, uint32_t b1)
{
    asm volatile(
        "mma.sync.aligned.m16n8k16.row.col.f32.bf16.bf16.f32 "
        "{%0,%1,%2,%3}, {%4,%5,%6,%7}, {%8,%9}, {%0,%1,%2,%3};"
        : "+f"(c[0]), "+f"(c[1]), "+f"(c[2]), "+f"(c[3])
        : "r"(a0), "r"(a1), "r"(a2), "r"(a3), "r"(b0), "r"(b1));
}
__device__ __forceinline__ uint32_t bits2(__nv_bfloat162 v) {
    return *reinterpret_cast<uint32_t*>(&v);
}

// ================= prestage: fp32 W -> bf16 hi/lo =================
__global__ __launch_bounds__(256) void conv_kernel(
    const float* __restrict__ Wq, const float* __restrict__ Wkv)
{
    int i4  = blockIdx.x * 256 + threadIdx.x;     // 0..98303 (float4 index)
    int idx = i4 * 4;                             // element index [h][m][n][k]
    int hm  = idx >> 14;                          // 0..23
    int h   = hm / 3, m = hm % 3;
    int nk  = idx & 16383;
    const float* src;
    float scl = 1.0f;
    if (m == 0)      src = Wq  + (size_t)h * 16384 + nk;
    else if (m == 1) { src = Wkv + (size_t)h * 32768 + nk; scl = SCALE; }
    else             src = Wkv + (size_t)h * 32768 + 16384 + nk;

    float4 f = *(const float4*)src;
    f.x *= scl; f.y *= scl; f.z *= scl; f.w *= scl;
    __nv_bfloat162 h01 = __floats2bfloat162_rn(f.x, f.y);
    __nv_bfloat162 h23 = __floats2bfloat162_rn(f.z, f.w);
    __nv_bfloat162 l01 = __floats2bfloat162_rn(f.x - __bfloat162float(h01.x),
                                               f.y - __bfloat162float(h01.y));
    __nv_bfloat162 l23 = __floats2bfloat162_rn(f.z - __bfloat162float(h23.x),
                                               f.w - __bfloat162float(h23.y));
    uint2 hv = make_uint2(bits2(h01), bits2(h23));
    uint2 lv = make_uint2(bits2(l01), bits2(l23));
    *(uint2*)(g_whi + idx) = hv;
    *(uint2*)(g_wlo + idx) = lv;
}

// ================= main kernel =================
__global__ __launch_bounds__(THREADS) void satt_kernel(
    const float* __restrict__ x,
    float* __restrict__ out)
{
    extern __shared__ char smem[];
    const uint32_t sbase = smem_u32(smem);
    const int tid  = threadIdx.x;
    const int wid  = tid >> 5, lane = tid & 31;
    const int g    = lane >> 2, tg = lane & 3;
    const int h    = blockIdx.y;
    const int b0   = blockIdx.x * NB;

    // ---- issue cp.async for W stage 0 (m=0, half=0) ----
    {
        const size_t wbase = (size_t)(h * 3 + 0) * 16384;   // +half*64
        #pragma unroll
        for (int j = 0; j < 4; ++j) {
            int c = tid + j * 512;               // 0..2047
            int sel = c >> 10, r = (c >> 3) & 127, ch = c & 7;
            const __nv_bfloat16* src = (sel ? g_wlo : g_whi) + wbase + (size_t)r * 128 + ch * 8;
            uint32_t dst = sbase + SM_WB + sel * 18432 + r * WROWB + ch * 16;
            cp_async16(dst, src);
        }
        CP_COMMIT();
    }

    // ---- stage x (hi/lo bf16) ----
    #pragma unroll
    for (int j = 0; j < 4; ++j) {
        int i4 = tid + j * 512;
        int b  = i4 >> 5, dq = (i4 & 31) * 4;
        float4 f = *(const float4*)(x + (size_t)(b0 + b) * CDIM + h * HD + dq);
        __nv_bfloat162 h01 = __floats2bfloat162_rn(f.x, f.y);
        __nv_bfloat162 h23 = __floats2bfloat162_rn(f.z, f.w);
        __nv_bfloat162 l01 = __floats2bfloat162_rn(f.x - __bfloat162float(h01.x),
                                                   f.y - __bfloat162float(h01.y));
        __nv_bfloat162 l23 = __floats2bfloat162_rn(f.z - __bfloat162float(h23.x),
                                                   f.w - __bfloat162float(h23.y));
        uint32_t* ph = (uint32_t*)(smem + SM_XHI + (size_t)(b * XPITCH + dq) * 2);
        uint32_t* pl = (uint32_t*)(smem + SM_XLO + (size_t)(b * XPITCH + dq) * 2);
        ph[0] = bits2(h01); ph[1] = bits2(h23);
        pl[0] = bits2(l01); pl[1] = bits2(l23);
    }

    const int mg = wid >> 3;              // 0/1: 32-batch half
    const int n0 = (wid & 7) * 16;        // 16 output cols per warp

    float acc[2][2][4];

    // ---- 6 pipelined stages: (m, K-half) ----
    for (int s = 0; s < 6; ++s) {
        const int m = s >> 1, half = s & 1;

        CP_WAIT0();
        __syncthreads();

        if (s < 5) {   // prefetch next stage into the other buffer
            const int ns = s + 1;
            const size_t wbase = (size_t)(h * 3 + (ns >> 1)) * 16384 + (ns & 1) * 64;
            const uint32_t dbuf = sbase + SM_WB + (ns & 1) * WBUF_SZ;
            #pragma unroll
            for (int j = 0; j < 4; ++j) {
                int c = tid + j * 512;
                int sel = c >> 10, r = (c >> 3) & 127, ch = c & 7;
                const __nv_bfloat16* src = (sel ? g_wlo : g_whi) + wbase + (size_t)r * 128 + ch * 8;
                uint32_t dst = dbuf + sel * 18432 + r * WROWB + ch * 16;
                cp_async16(dst, src);
            }
            CP_COMMIT();
        }

        if (half == 0) {
            #pragma unroll
            for (int a = 0; a < 2; ++a)
                #pragma unroll
                for (int b = 0; b < 2; ++b)
                    #pragma unroll
                    for (int c = 0; c < 4; ++c) acc[a][b][c] = 0.f;
        }

        const char* bufh = smem + SM_WB + (s & 1) * WBUF_SZ;
        const char* bufl = bufh + 18432;

        #pragma unroll
        for (int ktl = 0; ktl < 4; ++ktl) {
            const int k0  = half * 64 + ktl * 16;   // global K for A
            const int k0l = ktl * 16;               // local K for B
            uint32_t A[2][2][4];
            #pragma unroll
            for (int Mt = 0; Mt < 2; ++Mt) {
                int r = mg * 32 + Mt * 16 + g;
                const char* xh = smem + SM_XHI;
                const char* xl = smem + SM_XLO;
                A[Mt][0][0] = *(const uint32_t*)(xh + (size_t)(r * XPITCH + k0 + 2*tg) * 2);
                A[Mt][0][1] = *(const uint32_t*)(xh + (size_t)((r+8) * XPITCH + k0 + 2*tg) * 2);
                A[Mt][0][2] = *(const uint32_t*)(xh + (size_t)(r * XPITCH + k0 + 8 + 2*tg) * 2);
                A[Mt][0][3] = *(const uint32_t*)(xh + (size_t)((r+8) * XPITCH + k0 + 8 + 2*tg) * 2);
                A[Mt][1][0] = *(const uint32_t*)(xl + (size_t)(r * XPITCH + k0 + 2*tg) * 2);
                A[Mt][1][1] = *(const uint32_t*)(xl + (size_t)((r+8) * XPITCH + k0 + 2*tg) * 2);
                A[Mt][1][2] = *(const uint32_t*)(xl + (size_t)(r * XPITCH + k0 + 8 + 2*tg) * 2);
                A[Mt][1][3] = *(const uint32_t*)(xl + (size_t)((r+8) * XPITCH + k0 + 8 + 2*tg) * 2);
            }
            uint32_t Bf[2][2][2];
            #pragma unroll
            for (int Nt = 0; Nt < 2; ++Nt) {
                int n = n0 + Nt * 8 + g;
                Bf[Nt][0][0] = *(const uint32_t*)(bufh + (size_t)n * WROWB + (k0l + 2*tg) * 2);
                Bf[Nt][0][1] = *(const uint32_t*)(bufh + (size_t)n * WROWB + (k0l + 8 + 2*tg) * 2);
                Bf[Nt][1][0] = *(const uint32_t*)(bufl + (size_t)n * WROWB + (k0l + 2*tg) * 2);
                Bf[Nt][1][1] = *(const uint32_t*)(bufl + (size_t)n * WROWB + (k0l + 8 + 2*tg) * 2);
            }
            #pragma unroll
            for (int Mt = 0; Mt < 2; ++Mt)
                #pragma unroll
                for (int Nt = 0; Nt < 2; ++Nt) {
                    mma_bf16(acc[Mt][Nt], A[Mt][0][0], A[Mt][0][1], A[Mt][0][2], A[Mt][0][3],
                             Bf[Nt][0][0], Bf[Nt][0][1]);   // hi*hi
                    mma_bf16(acc[Mt][Nt], A[Mt][0][0], A[Mt][0][1], A[Mt][0][2], A[Mt][0][3],
                             Bf[Nt][1][0], Bf[Nt][1][1]);   // hi*lo
                    mma_bf16(acc[Mt][Nt], A[Mt][1][0], A[Mt][1][1], A[Mt][1][2], A[Mt][1][3],
                             Bf[Nt][0][0], Bf[Nt][0][1]);   // lo*hi
                }
        }

        if (half == 1) {
            float* dst = (float*)(smem + SM_QKV) + (size_t)m * NB * QPITCH;
            #pragma unroll
            for (int Mt = 0; Mt < 2; ++Mt)
                #pragma unroll
                for (int Nt = 0; Nt < 2; ++Nt) {
                    int r = mg * 32 + Mt * 16 + g;
                    int c = n0 + Nt * 8 + 2 * tg;
                    dst[r * QPITCH + c]           = acc[Mt][Nt][0];
                    dst[r * QPITCH + c + 1]       = acc[Mt][Nt][1];
                    dst[(r + 8) * QPITCH + c]     = acc[Mt][Nt][2];
                    dst[(r + 8) * QPITCH + c + 1] = acc[Mt][Nt][3];
                }
        }
    }
    __syncthreads();

    // ================= epilogue: separable moment softmax =================
    const float* q_s = (const float*)(smem + SM_QKV);
    const float* k_s = q_s + NB * QPITCH;
    const float* v_s = q_s + 2 * NB * QPITCH;
    float* red  = (float*)(smem + SM_RED);
    float* coef = (float*)(smem + SM_COEF);
    float* outs = (float*)(smem + SM_OUTS);

    {   // Phase A: partial moments
        const int b = tid & 63, part = tid >> 6;
        float K1=0,K2=0,K3=0,K4=0,K5=0,K6=0;
        float S0=0,S1=0,S2=0,S3=0,S4=0,S5=0,S6=0;
        #pragma unroll
        for (int i = 0; i < 16; ++i) {
            int e = part * 16 + i;
            float kv = k_s[b * QPITCH + e];
            float vv = v_s[b * QPITCH + e];
            S0 += vv;
            float t = kv; K1 += t; S1 = fmaf(t, vv, S1);
            t *= kv;      K2 += t; S2 = fmaf(t, vv, S2);
            t *= kv;      K3 += t; S3 = fmaf(t, vv, S3);
            t *= kv;      K4 += t; S4 = fmaf(t, vv, S4);
            t *= kv;      K5 += t; S5 = fmaf(t, vv, S5);
            t *= kv;      K6 += t; S6 = fmaf(t, vv, S6);
        }
        float* r = red + ((size_t)part * 64 + b) * 13;
        r[0]=K1; r[1]=K2; r[2]=K3; r[3]=K4; r[4]=K5; r[5]=K6;
        r[6]=S0; r[7]=S1; r[8]=S2; r[9]=S3; r[10]=S4; r[11]=S5; r[12]=S6;
    }
    __syncthreads();

    if (tid < 64) {   // Phase B: combine + fold 1/n!
        float c[13];
        #pragma unroll
        for (int j = 0; j < 13; ++j) c[j] = 0.f;
        #pragma unroll
        for (int p = 0; p < 8; ++p) {
            const float* r = red + ((size_t)p * 64 + tid) * 13;
            #pragma unroll
            for (int j = 0; j < 13; ++j) c[j] += r[j];
        }
        float* cc = coef + tid * 13;
        cc[0] = c[0];               cc[1] = c[1] * 0.5f;
        cc[2] = c[2] * (1.f/6.f);   cc[3] = c[3] * (1.f/24.f);
        cc[4] = c[4] * (1.f/120.f); cc[5] = c[5] * (1.f/720.f);
        cc[6] = c[6];               cc[7] = c[7];
        cc[8] = c[8] * 0.5f;        cc[9] = c[9] * (1.f/6.f);
        cc[10]= c[10]* (1.f/24.f);  cc[11]= c[11]* (1.f/120.f);
        cc[12]= c[12]* (1.f/720.f);
    }
    __syncthreads();

    {   // Phase C: Horner
        const int b = tid & 63, part = tid >> 6;
        const float* cc = coef + b * 13;
        const float a1=cc[0],a2=cc[1],a3=cc[2],a4=cc[3],a5=cc[4],a6=cc[5];
        const float g0=cc[6],g1=cc[7],g2=cc[8],g3=cc[9],g4=cc[10],g5=cc[11],g6=cc[12];
        #pragma unroll
        for (int i = 0; i < 16; ++i) {
            int d = part * 16 + i;
            float q = q_s[b * QPITCH + d];
            float den = fmaf(a6, q, a5);
            den = fmaf(den, q, a4); den = fmaf(den, q, a3);
            den = fmaf(den, q, a2); den = fmaf(den, q, a1);
            den = fmaf(den, q, 128.0f);
            float num = fmaf(g6, q, g5);
            num = fmaf(num, q, g4); num = fmaf(num, q, g3);
            num = fmaf(num, q, g2); num = fmaf(num, q, g1);
            num = fmaf(num, q, g0);
            outs[b * QPITCH + d] = num * rcpf(den);
        }
    }
    __syncthreads();

    {   // coalesced copy out
        const int b = tid >> 3, ds = (tid & 7) * 16;
        float* dst = out + (size_t)(b0 + b) * CDIM + h * HD + ds;
        #pragma unroll
        for (int j = 0; j < 4; ++j) {
            float4 v;
            v.x = outs[b * QPITCH + ds + j*4 + 0];
            v.y = outs[b * QPITCH + ds + j*4 + 1];
            v.z = outs[b * QPITCH + ds + j*4 + 2];
            v.w = outs[b * QPITCH + ds + j*4 + 3];
            *(float4*)(dst + j*4) = v;
        }
    }
}

extern "C" void kernel_launch(void* const* d_in, const int* in_sizes, int n_in,
                              void* d_out, int out_size) {
    const float* x   = (const float*)d_in[0];
    const float* Wq  = (const float*)d_in[1];
    const float* Wkv = (const float*)d_in[2];
    float* out = (float*)d_out;

    conv_kernel<<<384, 256>>>(Wq, Wkv);

    cudaFuncSetAttribute(satt_kernel, cudaFuncAttributeMaxDynamicSharedMemorySize, SM_TOTAL);
    dim3 grid(BSZ / NB, NHEAD);
    satt_kernel<<<grid, THREADS, SM_TOTAL>>>(x, out);
}